// round 1
// baseline (speedup 1.0000x reference)
#include <cuda_runtime.h>
#include <math.h>

// Problem constants (fixed by the reference: B=16, N=4096, Z=128)
#define BB 16
#define NN 4096
#define ZZ 128

#define THREADS 256
#define Q 4                      // queries per thread (register-blocked)
#define CHUNK 2048               // opponents staged in smem per phase (32KB float4)
#define QTILE (THREADS * Q)      // 1024 queries per CTA
#define XTILES (NN / QTILE)      // 4
#define NCTAS (XTILES * BB * 2)  // 128

__device__ float g_partials[NCTAS];

// Each CTA: one (batch, direction, query-tile). Thread owns Q queries, sweeps
// all 4096 opponents from smem. Opponent stored as (-2x, -2y, -2z, |x|^2) so
// cand = rx - 2*dot(q,x) is exactly 3 FFMA. The query-norm term (ry / rx of
// the OTHER direction) is added once per query at the end, which together
// across both directions reconstructs the full Chamfer sum.
__global__ __launch_bounds__(THREADS)
void chamfer_kernel(const float* __restrict__ preds,
                    const float* __restrict__ gts)
{
    __shared__ float4 sx[CHUNK];
    __shared__ float red[THREADS];

    const int b   = blockIdx.y;
    const int dir = blockIdx.z;
    const float* __restrict__ qb = (dir == 0 ? preds : gts) + b * 3 * NN;
    const float* __restrict__ ob = (dir == 0 ? gts   : preds) + b * 3 * NN;

    const int tid = threadIdx.x;

    float qx[Q], qy[Q], qz[Q], mn[Q];
    const int m0 = blockIdx.x * QTILE + tid;
#pragma unroll
    for (int q = 0; q < Q; q++) {
        const int m = m0 + q * THREADS;
        qx[q] = qb[m];
        qy[q] = qb[NN + m];
        qz[q] = qb[2 * NN + m];
        mn[q] = 3.4e38f;
    }

    for (int c = 0; c < NN; c += CHUNK) {
        __syncthreads();
        // Stage opponent chunk: coalesced per-channel loads, pre-scale by -2,
        // precompute squared norm into .w
        for (int i = tid; i < CHUNK; i += THREADS) {
            const int n = c + i;
            const float x0 = ob[n];
            const float x1 = ob[NN + n];
            const float x2 = ob[2 * NN + n];
            sx[i] = make_float4(-2.0f * x0, -2.0f * x1, -2.0f * x2,
                                x0 * x0 + x1 * x1 + x2 * x2);
        }
        __syncthreads();

#pragma unroll 4
        for (int i = 0; i < CHUNK; i++) {
            const float4 p = sx[i];   // broadcast across the warp
#pragma unroll
            for (int q = 0; q < Q; q++) {
                float t = fmaf(p.x, qx[q],
                          fmaf(p.y, qy[q],
                          fmaf(p.z, qz[q], p.w)));
                mn[q] = fminf(mn[q], t);
            }
        }
    }

    // Per-thread partial: sum of mins plus this query's own squared norm
    // (covers the Sum(ry) / Sum(rx) terms exactly once across both dirs).
    float s = 0.0f;
#pragma unroll
    for (int q = 0; q < Q; q++) {
        s += mn[q] + qx[q] * qx[q] + qy[q] * qy[q] + qz[q] * qz[q];
    }

    // CTA tree reduction (deterministic; no float atomics)
    red[tid] = s;
    __syncthreads();
    for (int off = THREADS / 2; off > 0; off >>= 1) {
        if (tid < off) red[tid] += red[tid + off];
        __syncthreads();
    }
    if (tid == 0) {
        const int cid = blockIdx.x + XTILES * (blockIdx.y + BB * blockIdx.z);
        g_partials[cid] = red[0];
    }
}

// Single-CTA finalizer: sum CTA partials + KL divergence, write scalar.
__global__ __launch_bounds__(256)
void final_kernel(const float* __restrict__ mu,
                  const float* __restrict__ logvar,
                  float* __restrict__ out)
{
    __shared__ float red[256];
    const int tid = threadIdx.x;
    float s = 0.0f;

    for (int i = tid; i < NCTAS; i += 256) s += g_partials[i];

    for (int i = tid; i < BB * ZZ; i += 256) {
        const float m  = mu[i];
        const float lv = logvar[i];
        s += -0.5f * (1.0f + lv - m * m - expf(lv));
    }

    red[tid] = s;
    __syncthreads();
    for (int off = 128; off > 0; off >>= 1) {
        if (tid < off) red[tid] += red[tid + off];
        __syncthreads();
    }
    if (tid == 0) out[0] = red[0];
}

extern "C" void kernel_launch(void* const* d_in, const int* in_sizes, int n_in,
                              void* d_out, int out_size)
{
    const float* preds  = (const float*)d_in[0];   // [16, 3, 4096]
    const float* gts    = (const float*)d_in[1];   // [16, 3, 4096]
    const float* mu     = (const float*)d_in[2];   // [16, 128]
    const float* logvar = (const float*)d_in[3];   // [16, 128]
    float* out = (float*)d_out;

    dim3 grid(XTILES, BB, 2);
    chamfer_kernel<<<grid, THREADS>>>(preds, gts);
    final_kernel<<<1, 256>>>(mu, logvar, out);
}